// round 3
// baseline (speedup 1.0000x reference)
#include <cuda_runtime.h>
#include <math.h>

#define BB 2
#define SS 2048
#define HH 32
#define DD 128
#define BSZ 16
#define NBLKS 512
#define NB (SS/BSZ)                      /* 128 blocks per batch */

#define ATTN_ELEMS (BB*SS*HH*DD)         /* 16777216 */
#define CACHE_ELEMS (NBLKS*HH*DD*BSZ)    /* 33554432 */

// ---------------- scratch (device globals: no runtime allocation) ----------
__device__ float g_cos[SS*DD];
__device__ float g_sin[SS*DD];
__device__ float g_qrot[ATTN_ELEMS];
__device__ float g_krot[ATTN_ELEMS];
__device__ int   g_tables[BB*NB];

// ---------------- block-table dtype normalization ---------------------------
// jnp.int64 silently becomes int32 when x64 is disabled. Detect from the data:
// int64 layout has zero upper words at odd int32 indices; int32 data has
// distinct block ids so t32[1] and t32[3] cannot both be zero. Both probe
// reads are within bounds under either interpretation.
__global__ void table_norm_kernel(const void* __restrict__ t) {
    const int* t32 = (const int*)t;
    bool is64 = (t32[1] == 0 && t32[3] == 0);
    int i = blockIdx.x * blockDim.x + threadIdx.x;
    if (i < BB*NB) {
        g_tables[i] = is64 ? (int)((const long long*)t)[i] : t32[i];
    }
}

// ---------------- RoPE cos/sin table ---------------------------------------
// Matches JAX fp32 semantics: angle rounded to fp32, cos/sin evaluated in
// double then rounded to fp32.
__global__ void rope_table_kernel() {
    int s = blockIdx.x;          // 0..2047
    int d = threadIdx.x;         // 0..63
    double e = (double)d / 64.0;
    float inv_freq = (float)(1.0 / pow(10000.0, e));
    float freq = (float)s * inv_freq;             // fp32 rounding like JAX
    double sd, cd;
    sincos((double)freq, &sd, &cd);
    float c = (float)cd, sn = (float)sd;
    g_cos[s*DD + d]      = c;
    g_cos[s*DD + d + 64] = c;
    g_sin[s*DD + d]      = sn;
    g_sin[s*DD + d + 64] = sn;
}

// ---------------- RoPE application (q and k) --------------------------------
__global__ void rope_kernel(const float* __restrict__ q,
                            const float* __restrict__ k) {
    int idx = blockIdx.x * blockDim.x + threadIdx.x;
    if (idx >= ATTN_ELEMS) return;
    int d   = idx & (DD-1);
    int bsh = idx >> 7;              // (b*S+s)*H + h
    int s   = (bsh / HH) & (SS-1);
    float c  = g_cos[s*DD + d];
    float sn = g_sin[s*DD + d];
    int pidx   = (d < 64) ? idx + 64 : idx - 64;
    float sign = (d < 64) ? -1.0f : 1.0f;
    float qv = q[idx], qp = q[pidx];
    float kv = k[idx], kp = k[pidx];
    g_qrot[idx] = fmaf(sign*qp, sn, qv*c);
    g_krot[idx] = fmaf(sign*kp, sn, kv*c);
}

// ---------------- paged-cache scatter (k_rot and raw v) ---------------------
// cache[blk_id][h][d][p] = src[b, blk*16+p, h, d]; transpose via smem.
__global__ void scatter_kernel(const float* __restrict__ v,
                               float* __restrict__ kc_out,
                               float* __restrict__ vc_out) {
    int h   = blockIdx.x & (HH-1);
    int blk = (blockIdx.x >> 5) & (NB-1);
    int b   = blockIdx.x >> 12;
    long long blk_id = g_tables[b*NB + blk];

    __shared__ float sk[BSZ*129];
    __shared__ float sv[BSZ*129];

    for (int i = threadIdx.x; i < BSZ*DD; i += blockDim.x) {
        int p = i >> 7, d = i & (DD-1);
        int s = blk*BSZ + p;
        long long src = (((long long)(b*SS + s))*HH + h)*DD + d;
        sk[p*129 + d] = g_krot[src];
        sv[p*129 + d] = v[src];
    }
    __syncthreads();
    for (int i = threadIdx.x; i < BSZ*DD; i += blockDim.x) {
        int d = i >> 4, p = i & (BSZ-1);
        long long dst = ((blk_id*HH + h)*(long long)DD + d)*BSZ + p;
        kc_out[dst] = sk[p*129 + d];
        vc_out[dst] = sv[p*129 + d];
    }
}

// ---------------- causal flash attention (fp32 SIMT) ------------------------
// BM=64 q-rows per CTA, BN=32 keys per tile, 128 threads.
// thread = (r, qd): rows r and r+32, dims {4*i + qd}.
__global__ void __launch_bounds__(128) attn_kernel(const float* __restrict__ v,
                                                   float* __restrict__ out) {
    const int BM = 64, BN = 32;
    __shared__ float smem[BN*DD*2 + BN*BM];   // sK | sV | sS  (40KB)
    float* sK = smem;
    float* sV = smem + BN*DD;
    float* sS = smem + 2*BN*DD;               // layout [n][local_row 0..63]

    int bx = blockIdx.x;
    int qt = 31 - (bx & 31);        // reverse for load balance (big tiles first)
    int bh = bx >> 5;
    int b  = bh >> 5;
    int h  = bh & (HH-1);
    int tid = threadIdx.x;
    int r  = tid >> 2;              // 0..31
    int qd = tid & 3;

    int row0 = qt*BM + r;
    int row1 = row0 + 32;

    const float scale = 0.08838834764831845f;   // 1/sqrt(128)
    float Q0[32], Q1[32];
    {
        long long qb0 = (((long long)(b*SS + row0))*HH + h)*DD;
        long long qb1 = (((long long)(b*SS + row1))*HH + h)*DD;
        #pragma unroll
        for (int i = 0; i < 32; i++) {
            Q0[i] = g_qrot[qb0 + 4*i + qd] * scale;
            Q1[i] = g_qrot[qb1 + 4*i + qd] * scale;
        }
    }

    float O0[32], O1[32];
    #pragma unroll
    for (int i = 0; i < 32; i++) { O0[i] = 0.f; O1[i] = 0.f; }
    float m0 = -1e30f, m1 = -1e30f, l0 = 0.f, l1 = 0.f;

    int ntiles = (qt + 1) * 2;
    for (int t = 0; t < ntiles; t++) {
        int k0 = t * BN;
        __syncthreads();
        // load K/V tiles (coalesced float4)
        #pragma unroll
        for (int j = 0; j < 8; j++) {
            int fi  = j*128 + tid;
            int row = fi >> 5;
            int c4  = fi & 31;
            long long src = (((long long)(b*SS + k0 + row))*HH + h)*DD + c4*4;
            ((float4*)sK)[row*32 + c4] = *(const float4*)&g_krot[src];
            ((float4*)sV)[row*32 + c4] = *(const float4*)&v[src];
        }
        __syncthreads();

        // scores: each quad reduces a D-split dot product
        for (int n = 0; n < BN; n++) {
            float a0 = 0.f, a1 = 0.f;
            const float* kp = &sK[n*DD + qd];
            #pragma unroll
            for (int i = 0; i < 32; i++) {
                float kv = kp[4*i];
                a0 = fmaf(Q0[i], kv, a0);
                a1 = fmaf(Q1[i], kv, a1);
            }
            a0 += __shfl_xor_sync(0xffffffffu, a0, 1);
            a0 += __shfl_xor_sync(0xffffffffu, a0, 2);
            a1 += __shfl_xor_sync(0xffffffffu, a1, 1);
            a1 += __shfl_xor_sync(0xffffffffu, a1, 2);
            if (qd == 0) {
                int gc = k0 + n;
                sS[n*64 + r]      = (gc <= row0) ? a0 : -1e30f;
                sS[n*64 + r + 32] = (gc <= row1) ? a1 : -1e30f;
            }
        }
        __syncthreads();

        // online softmax update
        float tm0 = -1e30f, tm1 = -1e30f;
        for (int n = 0; n < BN; n++) {
            tm0 = fmaxf(tm0, sS[n*64 + r]);
            tm1 = fmaxf(tm1, sS[n*64 + r + 32]);
        }
        float mn0 = fmaxf(m0, tm0), mn1 = fmaxf(m1, tm1);
        float c0 = __expf(m0 - mn0), c1 = __expf(m1 - mn1);
        l0 *= c0; l1 *= c1;
        #pragma unroll
        for (int i = 0; i < 32; i++) { O0[i] *= c0; O1[i] *= c1; }
        m0 = mn0; m1 = mn1;

        for (int n = 0; n < BN; n++) {
            float p0 = __expf(sS[n*64 + r]      - mn0);
            float p1 = __expf(sS[n*64 + r + 32] - mn1);
            l0 += p0; l1 += p1;
            const float* vp = &sV[n*DD + qd];
            #pragma unroll
            for (int i = 0; i < 32; i++) {
                float vv = vp[4*i];
                O0[i] = fmaf(p0, vv, O0[i]);
                O1[i] = fmaf(p1, vv, O1[i]);
            }
        }
    }

    // epilogue: normalize, stage through smem, coalesced store
    float i0 = 1.f / l0, i1 = 1.f / l1;
    __syncthreads();
    #pragma unroll
    for (int i = 0; i < 32; i++) {
        smem[r*DD + 4*i + qd]        = O0[i] * i0;
        smem[(r+32)*DD + 4*i + qd]   = O1[i] * i1;
    }
    __syncthreads();
    #pragma unroll
    for (int j = 0; j < 16; j++) {
        int fi  = j*128 + tid;
        int row = fi >> 5;
        int c4  = fi & 31;
        long long dst = (((long long)(b*SS + qt*BM + row))*HH + h)*DD + c4*4;
        *(float4*)&out[dst] = ((float4*)smem)[row*32 + c4];
    }
}

// ---------------- launcher ---------------------------------------------------
extern "C" void kernel_launch(void* const* d_in, const int* in_sizes, int n_in,
                              void* d_out, int out_size) {
    const float* q  = (const float*)d_in[0];
    const float* k  = (const float*)d_in[1];
    const float* v  = (const float*)d_in[2];
    const float* kc = (const float*)d_in[3];
    const float* vc = (const float*)d_in[4];
    const void*  tables = d_in[6];
    float* out = (float*)d_out;

    bool do_cache = (out_size >= ATTN_ELEMS + 2*CACHE_ELEMS);
    float* kc_out = out + ATTN_ELEMS;
    float* vc_out = kc_out + CACHE_ELEMS;

    if (do_cache) {
        // untouched cache blocks must equal the input caches
        cudaMemcpyAsync(kc_out, kc, sizeof(float)*(size_t)CACHE_ELEMS,
                        cudaMemcpyDeviceToDevice, 0);
        cudaMemcpyAsync(vc_out, vc, sizeof(float)*(size_t)CACHE_ELEMS,
                        cudaMemcpyDeviceToDevice, 0);
    }

    table_norm_kernel<<<1, 256>>>(tables);
    rope_table_kernel<<<SS, 64>>>();
    rope_kernel<<<(ATTN_ELEMS + 255)/256, 256>>>(q, k);
    if (do_cache)
        scatter_kernel<<<BB*NB*HH, 256>>>(v, kc_out, vc_out);
    attn_kernel<<<BB*HH*(SS/64), 128>>>(v, out);
}

// round 6
// speedup vs baseline: 3.7072x; 3.7072x over previous
#include <cuda_runtime.h>
#include <math.h>
#include <stdint.h>

#define BB 2
#define SS 2048
#define HH 32
#define DD 128
#define BSZ 16
#define NBLKS 512
#define NB (SS/BSZ)

#define ATTN_ELEMS (BB*SS*HH*DD)
#define CACHE_ELEMS (NBLKS*HH*DD*BSZ)

// ---------------- scratch ----------------------------------------------------
__device__ float g_cos[SS*DD];
__device__ float g_sin[SS*DD];
__device__ float g_qrot[ATTN_ELEMS];
__device__ float g_krot[ATTN_ELEMS];
__device__ int   g_tables[BB*NB];

// ---------------- block-table dtype normalization ----------------------------
__global__ void table_norm_kernel(const void* __restrict__ t) {
    const int* t32 = (const int*)t;
    bool is64 = (t32[1] == 0 && t32[3] == 0);
    int i = blockIdx.x * blockDim.x + threadIdx.x;
    if (i < BB*NB) {
        g_tables[i] = is64 ? (int)((const long long*)t)[i] : t32[i];
    }
}

// ---------------- RoPE table -------------------------------------------------
__global__ void rope_table_kernel() {
    int s = blockIdx.x;
    int d = threadIdx.x;
    double e = (double)d / 64.0;
    float inv_freq = (float)(1.0 / pow(10000.0, e));
    float freq = (float)s * inv_freq;
    double sd, cd;
    sincos((double)freq, &sd, &cd);
    float c = (float)cd, sn = (float)sd;
    g_cos[s*DD + d]      = c;
    g_cos[s*DD + d + 64] = c;
    g_sin[s*DD + d]      = sn;
    g_sin[s*DD + d + 64] = sn;
}

// ---------------- RoPE apply -------------------------------------------------
__global__ void rope_kernel(const float* __restrict__ q,
                            const float* __restrict__ k) {
    int idx = blockIdx.x * blockDim.x + threadIdx.x;
    if (idx >= ATTN_ELEMS) return;
    int d   = idx & (DD-1);
    int bsh = idx >> 7;
    int s   = (bsh / HH) & (SS-1);
    float c  = g_cos[s*DD + d];
    float sn = g_sin[s*DD + d];
    int pidx   = (d < 64) ? idx + 64 : idx - 64;
    float sign = (d < 64) ? -1.0f : 1.0f;
    float qv = q[idx], qp = q[pidx];
    float kv = k[idx], kp = k[pidx];
    g_qrot[idx] = fmaf(sign*qp, sn, qv*c);
    g_krot[idx] = fmaf(sign*kp, sn, kv*c);
}

// ---------------- paged-cache scatter ----------------------------------------
__global__ void scatter_kernel(const float* __restrict__ v,
                               float* __restrict__ kc_out,
                               float* __restrict__ vc_out) {
    int h   = blockIdx.x & (HH-1);
    int blk = (blockIdx.x >> 5) & (NB-1);
    int b   = blockIdx.x >> 12;
    long long blk_id = g_tables[b*NB + blk];

    __shared__ float sk[BSZ*129];
    __shared__ float sv[BSZ*129];

    for (int i = threadIdx.x; i < BSZ*DD; i += blockDim.x) {
        int p = i >> 7, d = i & (DD-1);
        int s = blk*BSZ + p;
        long long src = (((long long)(b*SS + s))*HH + h)*DD + d;
        sk[p*129 + d] = g_krot[src];
        sv[p*129 + d] = v[src];
    }
    __syncthreads();
    for (int i = threadIdx.x; i < BSZ*DD; i += blockDim.x) {
        int d = i >> 4, p = i & (BSZ-1);
        long long dst = ((blk_id*HH + h)*(long long)DD + d)*BSZ + p;
        kc_out[dst] = sk[p*129 + d];
        vc_out[dst] = sv[p*129 + d];
    }
}

// ============================================================================
//         mma.sync tf32 flash attention (BM=128, BN=64, 8 warps)
// ============================================================================
#define KSTR 132                       /* K row stride in floats (528B)  */
#define VSTR 136                       /* V row stride in floats (544B)  */
#define KBYTES (64*KSTR*4)             /* 33792 */
#define VBYTES (64*VSTR*4)             /* 34816 */
#define BUFB   (KBYTES+VBYTES)         /* 68608 */
#define ATTN_SMEM (2*BUFB)             /* 137216 */

static __device__ __forceinline__ uint32_t f2tf32(float x) {
    uint32_t r;
    asm("cvt.rna.tf32.f32 %0, %1;" : "=r"(r) : "f"(x));
    return r;
}

static __device__ __forceinline__ float exp2_fast(float y) {
    float t = y + 12582912.0f;
    int   n = __float_as_int(t) - 0x4B400000;
    float f = y - (t - 12582912.0f);
    float p = 0.0013333558f;
    p = fmaf(p, f, 0.0096181291f);
    p = fmaf(p, f, 0.055504109f);
    p = fmaf(p, f, 0.24022651f);
    p = fmaf(p, f, 0.69314718f);
    p = fmaf(p, f, 1.0f);
    return __int_as_float(__float_as_int(p) + (n << 23));
}

static __device__ __forceinline__ void cp16(uint32_t dst, const float* src) {
    asm volatile("cp.async.ca.shared.global [%0], [%1], 16;"
                 :: "r"(dst), "l"(src) : "memory");
}

#define MMA_TF32(D, A, B0, B1) \
    asm volatile("mma.sync.aligned.m16n8k8.row.col.f32.tf32.tf32.f32 " \
        "{%0,%1,%2,%3}, {%4,%5,%6,%7}, {%8,%9}, {%0,%1,%2,%3};" \
        : "+f"(D[0]), "+f"(D[1]), "+f"(D[2]), "+f"(D[3]) \
        : "r"(A[0]), "r"(A[1]), "r"(A[2]), "r"(A[3]), "r"(B0), "r"(B1))

static __device__ __forceinline__ void load_tile_async(
        uint32_t sb_buf, int b, int h, int k0,
        const float* __restrict__ vsrc, int tid) {
    #pragma unroll
    for (int it = 0; it < 8; it++) {
        int idx = it*256 + tid;
        int key = idx >> 5, c4 = idx & 31;
        const float* ks = &g_krot[((size_t)((b*SS + k0 + key)*HH + h))*DD + 4*c4];
        cp16(sb_buf + (uint32_t)key*528 + (uint32_t)c4*16, ks);
    }
    #pragma unroll
    for (int it = 0; it < 8; it++) {
        int idx = it*256 + tid;
        int key = idx >> 5, c4 = idx & 31;
        const float* vs = &vsrc[((size_t)((b*SS + k0 + key)*HH + h))*DD + 4*c4];
        cp16(sb_buf + KBYTES + (uint32_t)key*544 + (uint32_t)c4*16, vs);
    }
    asm volatile("cp.async.commit_group;" ::: "memory");
}

__global__ void __launch_bounds__(256, 1)
attn_mma_kernel(const float* __restrict__ v, float* __restrict__ out) {
    extern __shared__ char sm[];
    uint32_t sb;
    asm("{ .reg .u64 t; cvta.to.shared.u64 t, %1; cvt.u32.u64 %0, t; }"
        : "=r"(sb) : "l"(sm));

    int tid  = threadIdx.x;
    int w    = tid >> 5;
    int lane = tid & 31;
    int gq   = lane >> 2;          // 0..7  (row in fragment group)
    int j    = lane & 3;           // 0..3  (col in fragment group)

    int bx = blockIdx.x;
    int qt = 15 - (bx & 15);       // reverse: heavy tiles first
    int bh = bx >> 4;
    int b  = bh >> 5;
    int h  = bh & (HH-1);
    int q0 = qt * 128;

    // ---- stage Q (tf32-rounded) into buf0 region, stride KSTR --------------
    {
        uint32_t* Qs = (uint32_t*)sm;
        #pragma unroll
        for (int it = 0; it < 16; it++) {
            int idx = it*256 + tid;
            int row = idx >> 5, c4 = idx & 31;
            size_t src = ((size_t)((b*SS + q0 + row)*HH + h))*DD + 4*c4;
            float4 qv = *(const float4*)&g_qrot[src];
            uint4 qo = make_uint4(f2tf32(qv.x), f2tf32(qv.y),
                                  f2tf32(qv.z), f2tf32(qv.w));
            *(uint4*)&Qs[(uint32_t)row*KSTR + 4*c4] = qo;
        }
    }
    __syncthreads();

    // ---- load Q A-fragments into registers ---------------------------------
    uint32_t qa[16][4];
    {
        const uint32_t* Qs = (const uint32_t*)sm;
        int r0 = 16*w + gq;
        #pragma unroll
        for (int kf = 0; kf < 16; kf++) {
            uint32_t base = (uint32_t)r0*KSTR + kf*8 + j;
            qa[kf][0] = Qs[base];
            qa[kf][1] = Qs[base + 8*KSTR];
            qa[kf][2] = Qs[base + 4];
            qa[kf][3] = Qs[base + 8*KSTR + 4];
        }
    }
    __syncthreads();   // buf0 free for tile loads

    float oacc[16][4];
    #pragma unroll
    for (int i = 0; i < 16; i++) {
        oacc[i][0] = 0.f; oacc[i][1] = 0.f; oacc[i][2] = 0.f; oacc[i][3] = 0.f;
    }
    float l0 = 0.f, l1 = 0.f;

    const float C = 0.12751743f;   // (1/sqrt(128)) * log2(e)
    int row0g = q0 + 16*w + gq;
    int row1g = row0g + 8;
    int ntiles = 2*qt + 2;

    load_tile_async(sb + 0*BUFB, b, h, 0, v, tid);

    for (int t = 0; t < ntiles; t++) {
        if (t + 1 < ntiles) {
            load_tile_async(sb + (uint32_t)((t+1)&1)*BUFB, b, h, (t+1)*64, v, tid);
            asm volatile("cp.async.wait_group 1;" ::: "memory");
        } else {
            asm volatile("cp.async.wait_group 0;" ::: "memory");
        }
        __syncthreads();

        uint32_t bufo = (uint32_t)(t&1)*BUFB;
        const uint32_t* Ku = (const uint32_t*)(sm + bufo);
        uint32_t*       Vu = (uint32_t*)(sm + bufo + KBYTES);

        // ---- QK^T : S[16 x 64] per warp ------------------------------------
        float sacc[8][4];
        #pragma unroll
        for (int nf = 0; nf < 8; nf++) {
            sacc[nf][0] = 0.f; sacc[nf][1] = 0.f;
            sacc[nf][2] = 0.f; sacc[nf][3] = 0.f;
        }
        #pragma unroll
        for (int nf = 0; nf < 8; nf++) {
            uint32_t kb = (uint32_t)(nf*8 + gq)*KSTR + j;
            #pragma unroll
            for (int kf = 0; kf < 16; kf++) {
                uint32_t b0 = Ku[kb + kf*8];
                uint32_t b1 = Ku[kb + kf*8 + 4];
                MMA_TF32(sacc[nf], qa[kf], b0, b1);
            }
        }

        // ---- rna-round V in place (removes truncation bias) ----------------
        #pragma unroll
        for (int it = 0; it < 32; it++) {
            int idx = it*256 + tid;
            int key = idx >> 7, d = idx & 127;
            uint32_t a = (uint32_t)key*VSTR + d;
            Vu[a] = f2tf32(__uint_as_float(Vu[a]));
        }
        __syncthreads();

        // ---- softmax (unnormalized) + remap D-frag -> A-frag ---------------
        bool maskt = (t >= 2*qt);
        int k0 = t * 64;
        uint32_t pa[8][4];
        int src0 = (lane & ~3) | (j >> 1);
        int src2 = src0 + 2;
        bool odd = (j & 1);
        #pragma unroll
        for (int nf = 0; nf < 8; nf++) {
            int c = k0 + 8*nf + 2*j;
            float p0 = exp2_fast(sacc[nf][0] * C);
            float p1 = exp2_fast(sacc[nf][1] * C);
            float p2 = exp2_fast(sacc[nf][2] * C);
            float p3 = exp2_fast(sacc[nf][3] * C);
            if (maskt) {
                if (c     > row0g) p0 = 0.f;
                if (c + 1 > row0g) p1 = 0.f;
                if (c     > row1g) p2 = 0.f;
                if (c + 1 > row1g) p3 = 0.f;
            }
            l0 += p0 + p1;
            l1 += p2 + p3;
            uint32_t t0 = f2tf32(p0), t1 = f2tf32(p1);
            uint32_t t2 = f2tf32(p2), t3 = f2tf32(p3);
            uint32_t x0 = __shfl_sync(0xffffffffu, t0, src0);
            uint32_t x1 = __shfl_sync(0xffffffffu, t1, src0);
            uint32_t y0 = __shfl_sync(0xffffffffu, t2, src0);
            uint32_t y1 = __shfl_sync(0xffffffffu, t3, src0);
            uint32_t z0 = __shfl_sync(0xffffffffu, t0, src2);
            uint32_t z1 = __shfl_sync(0xffffffffu, t1, src2);
            uint32_t w0 = __shfl_sync(0xffffffffu, t2, src2);
            uint32_t w1 = __shfl_sync(0xffffffffu, t3, src2);
            pa[nf][0] = odd ? x1 : x0;
            pa[nf][1] = odd ? y1 : y0;
            pa[nf][2] = odd ? z1 : z0;
            pa[nf][3] = odd ? w1 : w0;
        }

        // ---- P·V : O[16 x 128] += P[16 x 64] V[64 x 128] -------------------
        #pragma unroll
        for (int nf = 0; nf < 16; nf++) {
            uint32_t vb = (uint32_t)j*VSTR + nf*8 + gq;
            #pragma unroll
            for (int kf = 0; kf < 8; kf++) {
                uint32_t b0 = Vu[vb + (uint32_t)(kf*8)*VSTR];
                uint32_t b1 = Vu[vb + (uint32_t)(kf*8 + 4)*VSTR];
                MMA_TF32(oacc[nf], pa[kf], b0, b1);
            }
        }
        __syncthreads();   // protect buf before next tile's cp.async
    }

    // ---- epilogue -----------------------------------------------------------
    l0 += __shfl_xor_sync(0xffffffffu, l0, 1);
    l0 += __shfl_xor_sync(0xffffffffu, l0, 2);
    l1 += __shfl_xor_sync(0xffffffffu, l1, 1);
    l1 += __shfl_xor_sync(0xffffffffu, l1, 2);
    float inv0 = 1.0f / l0, inv1 = 1.0f / l1;

    size_t base0 = ((size_t)(b*SS + row0g)*HH + h)*DD;
    size_t base1 = ((size_t)(b*SS + row1g)*HH + h)*DD;
    #pragma unroll
    for (int nf = 0; nf < 16; nf++) {
        int col = 8*nf + 2*j;
        float2 o0 = make_float2(oacc[nf][0]*inv0, oacc[nf][1]*inv0);
        float2 o1 = make_float2(oacc[nf][2]*inv1, oacc[nf][3]*inv1);
        *(float2*)&out[base0 + col] = o0;
        *(float2*)&out[base1 + col] = o1;
    }
}

// ---------------- launcher ----------------------------------------------------
extern "C" void kernel_launch(void* const* d_in, const int* in_sizes, int n_in,
                              void* d_out, int out_size) {
    const float* q  = (const float*)d_in[0];
    const float* k  = (const float*)d_in[1];
    const float* v  = (const float*)d_in[2];
    const float* kc = (const float*)d_in[3];
    const float* vc = (const float*)d_in[4];
    const void*  tables = d_in[6];
    float* out = (float*)d_out;

    bool do_cache = (out_size >= ATTN_ELEMS + 2*CACHE_ELEMS);
    float* kc_out = out + ATTN_ELEMS;
    float* vc_out = kc_out + CACHE_ELEMS;

    if (do_cache) {
        cudaMemcpyAsync(kc_out, kc, sizeof(float)*(size_t)CACHE_ELEMS,
                        cudaMemcpyDeviceToDevice, 0);
        cudaMemcpyAsync(vc_out, vc, sizeof(float)*(size_t)CACHE_ELEMS,
                        cudaMemcpyDeviceToDevice, 0);
    }

    cudaFuncSetAttribute(attn_mma_kernel,
                         cudaFuncAttributeMaxDynamicSharedMemorySize, ATTN_SMEM);

    table_norm_kernel<<<1, 256>>>(tables);
    rope_table_kernel<<<SS, 64>>>();
    rope_kernel<<<(ATTN_ELEMS + 255)/256, 256>>>(q, k);
    if (do_cache)
        scatter_kernel<<<BB*NB*HH, 256>>>(v, kc_out, vc_out);
    attn_mma_kernel<<<BB*HH*(SS/128), 256, ATTN_SMEM>>>(v, out);
}

// round 8
// speedup vs baseline: 4.4371x; 1.1969x over previous
#include <cuda_runtime.h>
#include <math.h>
#include <stdint.h>

#define BB 2
#define SS 2048
#define HH 32
#define DD 128
#define BSZ 16
#define NBLKS 512
#define NB (SS/BSZ)

#define ATTN_ELEMS (BB*SS*HH*DD)
#define CACHE_ELEMS (NBLKS*HH*DD*BSZ)

// ---------------- scratch ----------------------------------------------------
__device__ float g_cos[SS*DD];
__device__ float g_sin[SS*DD];
__device__ float g_qrot[ATTN_ELEMS];
__device__ float g_krot[ATTN_ELEMS];
__device__ int   g_tables[BB*NB];
__device__ int   g_inv[NBLKS];

// ---------------- block-table normalization + inverse map --------------------
__global__ void table_init_kernel(const void* __restrict__ t) {
    int tid = threadIdx.x;
    if (tid < NBLKS) g_inv[tid] = -1;
    __syncthreads();
    if (tid < BB*NB) {
        const int* t32 = (const int*)t;
        bool is64 = (t32[1] == 0 && t32[3] == 0);
        int val = is64 ? (int)((const long long*)t)[tid] : t32[tid];
        g_tables[tid] = val;
        if (val >= 0 && val < NBLKS) g_inv[val] = tid;
    }
}

// ---------------- RoPE table -------------------------------------------------
__global__ void rope_table_kernel() {
    int s = blockIdx.x;
    int d = threadIdx.x;
    double e = (double)d / 64.0;
    float inv_freq = (float)(1.0 / pow(10000.0, e));
    float freq = (float)s * inv_freq;
    double sd, cd;
    sincos((double)freq, &sd, &cd);
    float c = (float)cd, sn = (float)sd;
    g_cos[s*DD + d]      = c;
    g_cos[s*DD + d + 64] = c;
    g_sin[s*DD + d]      = sn;
    g_sin[s*DD + d + 64] = sn;
}

// ---------------- RoPE apply -------------------------------------------------
__global__ void rope_kernel(const float* __restrict__ q,
                            const float* __restrict__ k) {
    int idx = blockIdx.x * blockDim.x + threadIdx.x;
    if (idx >= ATTN_ELEMS) return;
    int d   = idx & (DD-1);
    int bsh = idx >> 7;
    int s   = (bsh / HH) & (SS-1);
    float c  = g_cos[s*DD + d];
    float sn = g_sin[s*DD + d];
    int pidx   = (d < 64) ? idx + 64 : idx - 64;
    float sign = (d < 64) ? -1.0f : 1.0f;
    float qv = q[idx], qp = q[pidx];
    float kv = k[idx], kp = k[pidx];
    g_qrot[idx] = fmaf(sign*qp, sn, qv*c);
    g_krot[idx] = fmaf(sign*kp, sn, kv*c);
}

// ---------------- fused cache fill (copy-or-scatter, each block written once)
__global__ void cache_fill_kernel(const float* __restrict__ kc_in,
                                  const float* __restrict__ vc_in,
                                  const float* __restrict__ v,
                                  float* __restrict__ kc_out,
                                  float* __restrict__ vc_out) {
    int h   = blockIdx.x & (HH-1);
    int blk = blockIdx.x >> 5;
    int inv = g_inv[blk];
    size_t base = ((size_t)blk*HH + h) * (DD*BSZ);

    if (inv < 0) {
        const float4* ks = (const float4*)&kc_in[base];
        const float4* vs = (const float4*)&vc_in[base];
        float4* kd = (float4*)&kc_out[base];
        float4* vd = (float4*)&vc_out[base];
        for (int i = threadIdx.x; i < DD*BSZ/4; i += blockDim.x) {
            kd[i] = ks[i];
            vd[i] = vs[i];
        }
        return;
    }

    int b    = inv >> 7;
    int blkq = inv & (NB-1);

    __shared__ float sk[BSZ*129];
    __shared__ float sv[BSZ*129];

    for (int i = threadIdx.x; i < BSZ*DD; i += blockDim.x) {
        int p = i >> 7, d = i & (DD-1);
        int s = blkq*BSZ + p;
        size_t src = ((size_t)((b*SS + s)*HH + h))*DD + d;
        sk[p*129 + d] = g_krot[src];
        sv[p*129 + d] = v[src];
    }
    __syncthreads();
    for (int i = threadIdx.x; i < BSZ*DD; i += blockDim.x) {
        int d = i >> 4, p = i & (BSZ-1);
        kc_out[base + (size_t)d*BSZ + p] = sk[p*129 + d];
        vc_out[base + (size_t)d*BSZ + p] = sv[p*129 + d];
    }
}

// ============================================================================
//   flash attention: tf32 mma QK + tf32 mma PV (BM=128, BN=64, 8 warps)
//   K double-buffered via cp.async; V direct LDG->regs->single STS.
// ============================================================================
#define KSTR 132                        /* K/Q row stride, floats (528B) */
#define KBYTES (64*KSTR*4)              /* 33792 */
#define VTSTR 136                       /* V row stride, floats (8 mod 32) */
#define VTBYTES (64*VTSTR*4)            /* 34816 */
#define ATTN_SMEM (2*KBYTES + VTBYTES)  /* 102400 */

static __device__ __forceinline__ uint32_t f2tf32(float x) {
    uint32_t r;
    asm("cvt.rna.tf32.f32 %0, %1;" : "=r"(r) : "f"(x));
    return r;
}

static __device__ __forceinline__ float exp2_fast(float y) {
    float t = y + 12582912.0f;
    int   n = __float_as_int(t) - 0x4B400000;
    float f = y - (t - 12582912.0f);
    float p = 0.0013333558f;
    p = fmaf(p, f, 0.0096181291f);
    p = fmaf(p, f, 0.055504109f);
    p = fmaf(p, f, 0.24022651f);
    p = fmaf(p, f, 0.69314718f);
    p = fmaf(p, f, 1.0f);
    return __int_as_float(__float_as_int(p) + (n << 23));
}

static __device__ __forceinline__ void cp16(uint32_t dst, const float* src) {
    asm volatile("cp.async.ca.shared.global [%0], [%1], 16;"
                 :: "r"(dst), "l"(src) : "memory");
}

#define MMA_TF32(D, A, B0, B1) \
    asm volatile("mma.sync.aligned.m16n8k8.row.col.f32.tf32.tf32.f32 " \
        "{%0,%1,%2,%3}, {%4,%5,%6,%7}, {%8,%9}, {%0,%1,%2,%3};" \
        : "+f"(D[0]), "+f"(D[1]), "+f"(D[2]), "+f"(D[3]) \
        : "r"(A[0]), "r"(A[1]), "r"(A[2]), "r"(A[3]), "r"(B0), "r"(B1))

static __device__ __forceinline__ void load_k_async(uint32_t sb_buf, int b,
                                                    int h, int k0, int tid) {
    #pragma unroll
    for (int it = 0; it < 8; it++) {
        int idx = it*256 + tid;
        int key = idx >> 5, c4 = idx & 31;
        const float* ks = &g_krot[((size_t)((b*SS + k0 + key)*HH + h))*DD + 4*c4];
        cp16(sb_buf + (uint32_t)key*(KSTR*4) + (uint32_t)c4*16, ks);
    }
    asm volatile("cp.async.commit_group;" ::: "memory");
}

__global__ void __launch_bounds__(256, 1)
attn_mma_kernel(const float* __restrict__ v, float* __restrict__ out) {
    extern __shared__ char sm[];
    uint32_t sb;
    asm("{ .reg .u64 t; cvta.to.shared.u64 t, %1; cvt.u32.u64 %0, t; }"
        : "=r"(sb) : "l"(sm));

    int tid  = threadIdx.x;
    int w    = tid >> 5;
    int lane = tid & 31;
    int gq   = lane >> 2;          // 0..7
    int j    = lane & 3;           // 0..3

    int bx = blockIdx.x;
    int qt = 15 - (bx & 15);       // reverse: heavy tiles first
    int bh = bx >> 4;
    int b  = bh >> 5;
    int h  = bh & (HH-1);
    int q0 = qt * 128;

    // ---- stage Q (tf32) in the K double-buffer region ----------------------
    {
        uint32_t* Qs = (uint32_t*)sm;
        #pragma unroll
        for (int it = 0; it < 16; it++) {
            int idx = it*256 + tid;
            int row = idx >> 5, c4 = idx & 31;
            size_t src = ((size_t)((b*SS + q0 + row)*HH + h))*DD + 4*c4;
            float4 qv = *(const float4*)&g_qrot[src];
            uint4 qo = make_uint4(f2tf32(qv.x), f2tf32(qv.y),
                                  f2tf32(qv.z), f2tf32(qv.w));
            *(uint4*)&Qs[(uint32_t)row*KSTR + 4*c4] = qo;
        }
    }
    __syncthreads();

    // ---- Q A-fragments to registers ---------------------------------------
    uint32_t qa[16][4];
    {
        const uint32_t* Qs = (const uint32_t*)sm;
        int r0 = 16*w + gq;
        #pragma unroll
        for (int kf = 0; kf < 16; kf++) {
            uint32_t base = (uint32_t)r0*KSTR + kf*8 + j;
            qa[kf][0] = Qs[base];
            qa[kf][1] = Qs[base + 8*KSTR];
            qa[kf][2] = Qs[base + 4];
            qa[kf][3] = Qs[base + 8*KSTR + 4];
        }
    }
    __syncthreads();   // Q staging region free -> K double buffers

    float oacc[16][4];
    #pragma unroll
    for (int i = 0; i < 16; i++) {
        oacc[i][0] = 0.f; oacc[i][1] = 0.f; oacc[i][2] = 0.f; oacc[i][3] = 0.f;
    }
    float l0 = 0.f, l1 = 0.f;

    const float C = 0.12751743f;   // (1/sqrt(128)) * log2(e)
    int row0g = q0 + 16*w + gq;
    int row1g = row0g + 8;
    int ntiles = 2*qt + 2;

    // V load geometry: thread handles keys 2kp,2kp+1, dims {it*32+dq..+3}
    int kp = tid >> 3;             // 0..31
    int dq = (tid & 7) * 4;        // 0,4,...,28

    load_k_async(sb, b, h, 0, tid);

    for (int t = 0; t < ntiles; t++) {
        if (t + 1 < ntiles) {
            load_k_async(sb + (uint32_t)((t+1)&1)*KBYTES, b, h, (t+1)*64, tid);
            asm volatile("cp.async.wait_group 1;" ::: "memory");
        } else {
            asm volatile("cp.async.wait_group 0;" ::: "memory");
        }
        __syncthreads();   // K(t) ready; PV(t-1) done so Vt is writable

        int k0 = t * 64;
        const uint32_t* Ku = (const uint32_t*)(sm + (uint32_t)(t&1)*KBYTES);
        uint32_t*       Vt = (uint32_t*)(sm + 2*KBYTES);

        // ---- issue V global loads (latency hidden under QK MMA) ------------
        uint4 va[4], vb4[4];
        {
            size_t rb0 = ((size_t)((b*SS + k0 + 2*kp)*HH + h))*DD;
            size_t rb1 = rb0 + (size_t)HH*DD;
            #pragma unroll
            for (int it = 0; it < 4; it++) {
                int d = it*32 + dq;
                va[it]  = *(const uint4*)&v[rb0 + d];
                vb4[it] = *(const uint4*)&v[rb1 + d];
            }
        }

        // ---- QK^T : S[16 x 64] per warp (tf32) -----------------------------
        float sacc[8][4];
        #pragma unroll
        for (int nf = 0; nf < 8; nf++) {
            sacc[nf][0] = 0.f; sacc[nf][1] = 0.f;
            sacc[nf][2] = 0.f; sacc[nf][3] = 0.f;
        }
        #pragma unroll
        for (int nf = 0; nf < 8; nf++) {
            uint32_t kb = (uint32_t)(nf*8 + gq)*KSTR + j;
            #pragma unroll
            for (int kf = 0; kf < 16; kf++) {
                uint32_t b0 = Ku[kb + kf*8];
                uint32_t b1 = Ku[kb + kf*8 + 4];
                MMA_TF32(sacc[nf], qa[kf], b0, b1);
            }
        }

        // ---- convert V (rna tf32) -> Vt[key][d] ----------------------------
        #pragma unroll
        for (int it = 0; it < 4; it++) {
            int d = it*32 + dq;
            uint4 w0 = make_uint4(f2tf32(__uint_as_float(va[it].x)),
                                  f2tf32(__uint_as_float(va[it].y)),
                                  f2tf32(__uint_as_float(va[it].z)),
                                  f2tf32(__uint_as_float(va[it].w)));
            uint4 w1 = make_uint4(f2tf32(__uint_as_float(vb4[it].x)),
                                  f2tf32(__uint_as_float(vb4[it].y)),
                                  f2tf32(__uint_as_float(vb4[it].z)),
                                  f2tf32(__uint_as_float(vb4[it].w)));
            *(uint4*)&Vt[(uint32_t)(2*kp)*VTSTR + d]     = w0;
            *(uint4*)&Vt[(uint32_t)(2*kp + 1)*VTSTR + d] = w1;
        }

        // ---- softmax (unnormalized) + remap D-frag -> A-frag ---------------
        bool maskt = (t >= 2*qt);
        uint32_t pa[8][4];
        int src0 = (lane & ~3) | (j >> 1);
        int src2 = src0 + 2;
        bool odd = (j & 1);
        #pragma unroll
        for (int nf = 0; nf < 8; nf++) {
            int c = k0 + 8*nf + 2*j;
            float p0 = exp2_fast(sacc[nf][0] * C);
            float p1 = exp2_fast(sacc[nf][1] * C);
            float p2 = exp2_fast(sacc[nf][2] * C);
            float p3 = exp2_fast(sacc[nf][3] * C);
            if (maskt) {
                if (c     > row0g) p0 = 0.f;
                if (c + 1 > row0g) p1 = 0.f;
                if (c     > row1g) p2 = 0.f;
                if (c + 1 > row1g) p3 = 0.f;
            }
            uint32_t t0 = f2tf32(p0), t1 = f2tf32(p1);
            uint32_t t2 = f2tf32(p2), t3 = f2tf32(p3);
            // accumulate l from the ROUNDED weights (numerator consistency)
            l0 += __uint_as_float(t0) + __uint_as_float(t1);
            l1 += __uint_as_float(t2) + __uint_as_float(t3);
            uint32_t x0 = __shfl_sync(0xffffffffu, t0, src0);
            uint32_t x1 = __shfl_sync(0xffffffffu, t1, src0);
            uint32_t y0 = __shfl_sync(0xffffffffu, t2, src0);
            uint32_t y1 = __shfl_sync(0xffffffffu, t3, src0);
            uint32_t z0 = __shfl_sync(0xffffffffu, t0, src2);
            uint32_t z1 = __shfl_sync(0xffffffffu, t1, src2);
            uint32_t w0 = __shfl_sync(0xffffffffu, t2, src2);
            uint32_t w1 = __shfl_sync(0xffffffffu, t3, src2);
            pa[nf][0] = odd ? x1 : x0;
            pa[nf][1] = odd ? y1 : y0;
            pa[nf][2] = odd ? z1 : z0;
            pa[nf][3] = odd ? w1 : w0;
        }
        __syncthreads();   // Vt visible to all warps

        // ---- P·V : O[16 x 128] += P[16 x 64] V[64 x 128] (tf32) ------------
        #pragma unroll
        for (int nf = 0; nf < 16; nf++) {
            uint32_t vbs = (uint32_t)j*VTSTR + nf*8 + gq;
            #pragma unroll
            for (int kf = 0; kf < 8; kf++) {
                uint32_t b0 = Vt[vbs + (uint32_t)(kf*8)*VTSTR];
                uint32_t b1 = Vt[vbs + (uint32_t)(kf*8 + 4)*VTSTR];
                MMA_TF32(oacc[nf], pa[kf], b0, b1);
            }
        }
        // loop-top __syncthreads protects Vt and the K buffer being refilled
    }

    // ---- epilogue ----------------------------------------------------------
    l0 += __shfl_xor_sync(0xffffffffu, l0, 1);
    l0 += __shfl_xor_sync(0xffffffffu, l0, 2);
    l1 += __shfl_xor_sync(0xffffffffu, l1, 1);
    l1 += __shfl_xor_sync(0xffffffffu, l1, 2);
    float inv0 = 1.0f / l0, inv1 = 1.0f / l1;

    size_t base0 = ((size_t)(b*SS + row0g)*HH + h)*DD;
    size_t base1 = ((size_t)(b*SS + row1g)*HH + h)*DD;
    #pragma unroll
    for (int nf = 0; nf < 16; nf++) {
        int col = 8*nf + 2*j;
        float2 o0 = make_float2(oacc[nf][0]*inv0, oacc[nf][1]*inv0);
        float2 o1 = make_float2(oacc[nf][2]*inv1, oacc[nf][3]*inv1);
        *(float2*)&out[base0 + col] = o0;
        *(float2*)&out[base1 + col] = o1;
    }
}

// ---------------- launcher ----------------------------------------------------
extern "C" void kernel_launch(void* const* d_in, const int* in_sizes, int n_in,
                              void* d_out, int out_size) {
    const float* q  = (const float*)d_in[0];
    const float* k  = (const float*)d_in[1];
    const float* v  = (const float*)d_in[2];
    const float* kc = (const float*)d_in[3];
    const float* vc = (const float*)d_in[4];
    const void*  tables = d_in[6];
    float* out = (float*)d_out;

    bool do_cache = (out_size >= ATTN_ELEMS + 2*CACHE_ELEMS);
    float* kc_out = out + ATTN_ELEMS;
    float* vc_out = kc_out + CACHE_ELEMS;

    cudaFuncSetAttribute(attn_mma_kernel,
                         cudaFuncAttributeMaxDynamicSharedMemorySize, ATTN_SMEM);

    table_init_kernel<<<1, 512>>>(tables);
    rope_table_kernel<<<SS, 64>>>();
    rope_kernel<<<(ATTN_ELEMS + 255)/256, 256>>>(q, k);
    if (do_cache)
        cache_fill_kernel<<<NBLKS*HH, 128>>>(kc, vc, v, kc_out, vc_out);
    attn_mma_kernel<<<BB*HH*(SS/128), 256, ATTN_SMEM>>>(v, out);
}